// round 7
// baseline (speedup 1.0000x reference)
#include <cuda_runtime.h>
#include <cuda_fp16.h>
#include <cstdint>
#include <math.h>

#define N_TOK 4096
#define DIM   2048
#define FF    1024
#define NE    16
#define CAP   4096

// half-buffer offsets (in halves)
#define OXH  0ull
#define ORG  (8ull  << 20)
#define ORW1 (40ull << 20)
#define ORW2 (72ull << 20)
#define OSG  (104ull << 20)
#define OSW1 (108ull << 20)
#define OSW2 (112ull << 20)

__device__ int    g_cnt[NE];
__device__ int    g_list[NE * CAP];
__device__ float  g_wt[NE * CAP];
__device__ __half g_half[116ull << 20];
__device__ __half g_hh[(size_t)NE * CAP * FF];      // routed hidden
__device__ __half g_hs[(size_t)N_TOK * 2 * FF];     // shared hidden (separate!)

// ---------- helpers ----------
__device__ __forceinline__ uint32_t smem_u32(const void* p) {
    uint32_t a;
    asm("{ .reg .u64 t; cvta.to.shared.u64 t, %1; cvt.u32.u64 %0, t; }" : "=r"(a) : "l"(p));
    return a;
}
__device__ __forceinline__ void cp16(uint32_t dst, const void* src) {
    asm volatile("cp.async.cg.shared.global [%0], [%1], 16;" :: "r"(dst), "l"(src));
}
__device__ __forceinline__ void ldm4(uint32_t* r, uint32_t a) {
    asm volatile("ldmatrix.sync.aligned.m8n8.x4.shared.b16 {%0,%1,%2,%3}, [%4];"
                 : "=r"(r[0]), "=r"(r[1]), "=r"(r[2]), "=r"(r[3]) : "r"(a));
}
__device__ __forceinline__ void ldm4t(uint32_t* r, uint32_t a) {
    asm volatile("ldmatrix.sync.aligned.m8n8.x4.trans.shared.b16 {%0,%1,%2,%3}, [%4];"
                 : "=r"(r[0]), "=r"(r[1]), "=r"(r[2]), "=r"(r[3]) : "r"(a));
}
__device__ __forceinline__ void mma16(float* d, const uint32_t* a, uint32_t b0, uint32_t b1) {
    asm volatile("mma.sync.aligned.m16n8k16.row.col.f32.f16.f16.f32 "
                 "{%0,%1,%2,%3},{%4,%5,%6,%7},{%8,%9},{%0,%1,%2,%3};"
                 : "+f"(d[0]), "+f"(d[1]), "+f"(d[2]), "+f"(d[3])
                 : "r"(a[0]), "r"(a[1]), "r"(a[2]), "r"(a[3]), "r"(b0), "r"(b1));
}
__device__ __forceinline__ float gelu_exact(float v) {
    return 0.5f * v * (1.0f + erff(v * 0.70710678118654752440f));
}
#define COMMIT() asm volatile("cp.async.commit_group;" ::: "memory")
#define WAIT1()  asm volatile("cp.async.wait_group 1;" ::: "memory")

// ---------- conversion / copy ----------
__global__ void cvt_kernel(const float* __restrict__ src, size_t dofs, size_t n) {
    size_t i = ((size_t)blockIdx.x * 256 + threadIdx.x) * 4;
    if (i >= n) return;
    float4 v = *(const float4*)(src + i);
    __half2* d = (__half2*)(g_half + dofs + i);
    d[0] = __floats2half2_rn(v.x, v.y);
    d[1] = __floats2half2_rn(v.z, v.w);
}
__global__ void copy_x_kernel(const float* __restrict__ x, float* __restrict__ out) {
    size_t i = ((size_t)blockIdx.x * 256 + threadIdx.x) * 4;
    *(float4*)(out + i) = *(const float4*)(x + i);
}

// ---------- router ----------
__global__ void zero_cnt_kernel() { if (threadIdx.x < NE) g_cnt[threadIdx.x] = 0; }

__global__ void router_kernel(const float* __restrict__ x, const float* __restrict__ wa) {
    int t = (blockIdx.x * blockDim.x + threadIdx.x) >> 5;
    int lane = threadIdx.x & 31;
    if (t >= N_TOK) return;
    float acc[NE];
#pragma unroll
    for (int e = 0; e < NE; e++) acc[e] = 0.0f;
    const float* xr = x + (size_t)t * DIM;
    for (int d = lane; d < DIM; d += 32) {
        float xv = xr[d];
#pragma unroll
        for (int e = 0; e < NE; e++) acc[e] += xv * wa[(size_t)d * NE + e];
    }
#pragma unroll
    for (int e = 0; e < NE; e++)
#pragma unroll
        for (int o = 16; o > 0; o >>= 1) acc[e] += __shfl_xor_sync(0xffffffffu, acc[e], o);
    if (lane == 0) {
        float aff[NE];
#pragma unroll
        for (int e = 0; e < NE; e++) aff[e] = 1.0f / (1.0f + expf(-acc[e]));
        int e1 = 0; float p1 = aff[0];
#pragma unroll
        for (int e = 1; e < NE; e++) if (aff[e] > p1) { p1 = aff[e]; e1 = e; }
        int e2 = (e1 == 0) ? 1 : 0; float p2 = aff[e2];
#pragma unroll
        for (int e = 0; e < NE; e++) if (e != e1 && aff[e] > p2) { p2 = aff[e]; e2 = e; }
        float inv = 1.0f / (p1 + p2);
        int q1 = atomicAdd(&g_cnt[e1], 1);
        g_list[e1 * CAP + q1] = t; g_wt[e1 * CAP + q1] = p1 * inv;
        int q2 = atomicAdd(&g_cnt[e2], 1);
        g_list[e2 * CAP + q2] = t; g_wt[e2 * CAP + q2] = p2 * inv;
    }
}

// ================= tile bodies (round-6 proven mappings) =================
// One 128x128(x K) tile: A rows via s_row, B dual (up) or single (down).

__device__ __forceinline__ void tile_up(
    int m0, int n0f, int rows, const int* list,
    const __half* G, const __half* W,
    const float* b0, const float* b1,
    __half* hbase, int hstride,
    uint32_t sbase, int* s_row, int tid, int wid, int lane)
{
    { int mm = m0 + tid; s_row[tid] = list ? list[mm < rows ? mm : m0] : mm; }
    __syncthreads();

    const __half* Ah = g_half + OXH;
    int rix[8];
#pragma unroll
    for (int i = 0; i < 8; i++) rix[i] = s_row[(tid >> 3) + i * 16];

    const int c = tid & 15;
    const int f0 = n0f + ((c >> 1) >> 1) * 16 + (c & 1) * 8;
    const __half* Bb = (((c >> 1) & 1) ? W : G) + f0;
    const int akseg = tid & 7, arow = tid >> 3, kroww = tid >> 4;
    const uint32_t a_dst = (uint32_t)(arow * 128 + ((akseg * 16) ^ ((arow & 7) << 4)));
    const uint32_t b_dst = (uint32_t)(16384 + kroww * 256 + ((c * 16) ^ (kroww << 4)));

#define UISSUE(k0g, buf) do { \
    uint32_t sB_ = sbase + (uint32_t)(buf) * 32768u; \
    _Pragma("unroll") \
    for (int i_ = 0; i_ < 8; i_++) { \
        cp16(sB_ + a_dst + (uint32_t)i_ * 2048u, Ah + (size_t)rix[i_] * DIM + (k0g) + akseg * 8); \
        cp16(sB_ + b_dst + (uint32_t)i_ * 2048u, Bb + (size_t)((k0g) + kroww + i_ * 8) * FF); \
    } \
} while (0)

    const int wm = wid & 1, wn = wid >> 1;
    const int m_off = wm * 64;
    uint32_t aoffc[4], axorl[4];
#pragma unroll
    for (int mi = 0; mi < 4; mi++) {
        int ar = m_off + mi * 16 + (lane & 15);
        aoffc[mi] = (uint32_t)(ar * 128);
        axorl[mi] = (uint32_t)((ar & 7) << 4);
    }
    const uint32_t akp = (uint32_t)((lane >> 4) * 16);
    const int kr0 = ((lane >> 3) & 1) * 8 + (lane & 7);
    const int noct = (lane >> 4) & 1;
    uint32_t boffc[4];
#pragma unroll
    for (int g = 0; g < 4; g++) {
        int nb = wn * 64 + g * 16;
        uint32_t nbyte = (uint32_t)((nb + noct * 8) * 2);
        boffc[g] = 16384u + (uint32_t)(kr0 * 256) + (nbyte ^ (uint32_t)((kr0 & 7) << 4));
    }

    float acc[32][4];
#pragma unroll
    for (int i = 0; i < 32; i++)
#pragma unroll
        for (int j = 0; j < 4; j++) acc[i][j] = 0.0f;

    UISSUE(0, 0);  COMMIT();
    UISSUE(64, 1); COMMIT();
    for (int it = 0; it < DIM / 64; it++) {
        WAIT1();
        __syncthreads();
        if (it + 2 < DIM / 64) UISSUE((it + 2) * 64, (it + 2) % 3);
        COMMIT();
        const uint32_t sb = sbase + (uint32_t)(it % 3) * 32768u;
#pragma unroll
        for (int ks = 0; ks < 4; ks++) {
            uint32_t af[4][4];
#pragma unroll
            for (int mi = 0; mi < 4; mi++)
                ldm4(af[mi], sb + aoffc[mi] + (((uint32_t)(ks * 32) + akp) ^ axorl[mi]));
            uint32_t bf[4][4];
#pragma unroll
            for (int g = 0; g < 4; g++)
                ldm4t(bf[g], sb + boffc[g] + (uint32_t)(ks * 4096));
#pragma unroll
            for (int mi = 0; mi < 4; mi++)
#pragma unroll
                for (int nt = 0; nt < 8; nt++)
                    mma16(acc[mi * 8 + nt], af[mi],
                          bf[nt >> 1][(nt & 1) * 2], bf[nt >> 1][(nt & 1) * 2 + 1]);
        }
    }
#undef UISSUE

    const int rbase = lane >> 2;
    const int cbase = (lane & 3) * 2;
#pragma unroll
    for (int mi = 0; mi < 4; mi++) {
#pragma unroll
        for (int h = 0; h < 2; h++) {
            const int m = m0 + m_off + mi * 16 + rbase + h * 8;
            if (m >= rows) continue;
#pragma unroll
            for (int gi = 0; gi < 4; gi++) {
                const int g = (gi & 1) + (gi >> 1) * 4;  // 0,1,4,5
                const int f = n0f + wn * 32 + (g >> 2) * 16 + (g & 1) * 8 + cbase;
                float c1a = acc[mi * 8 + g][h * 2 + 0] + b0[f];
                float c1b = acc[mi * 8 + g][h * 2 + 1] + b0[f + 1];
                float c2a = acc[mi * 8 + g + 2][h * 2 + 0] + b1[f];
                float c2b = acc[mi * 8 + g + 2][h * 2 + 1] + b1[f + 1];
                __half2 hv = __floats2half2_rn(gelu_exact(c1a) * c2a, gelu_exact(c1b) * c2b);
                *(__half2*)(hbase + (size_t)m * hstride + f) = hv;
            }
        }
    }
}

__device__ __forceinline__ void tile_down(
    int m0, int n0f, int rows, int kt,
    const __half* Ah, int lda,
    const int* list, const float* wtp,
    const __half* B, const float* b2, const float* b2b,
    float* outp,
    uint32_t sbase, int* s_row, int tid, int wid, int lane)
{
    s_row[tid] = m0 + tid;
    __syncthreads();

    int rix[8];
#pragma unroll
    for (int i = 0; i < 8; i++) rix[i] = s_row[(tid >> 3) + i * 16];

    const int c = tid & 15;
    const __half* Bb = B + n0f + c * 8;
    const int akseg = tid & 7, arow = tid >> 3, kroww = tid >> 4;
    const uint32_t a_dst = (uint32_t)(arow * 128 + ((akseg * 16) ^ ((arow & 7) << 4)));
    const uint32_t b_dst = (uint32_t)(16384 + kroww * 256 + ((c * 16) ^ (kroww << 4)));

#define DISSUE(k0g, buf) do { \
    uint32_t sB_ = sbase + (uint32_t)(buf) * 32768u; \
    _Pragma("unroll") \
    for (int i_ = 0; i_ < 8; i_++) { \
        cp16(sB_ + a_dst + (uint32_t)i_ * 2048u, Ah + (size_t)rix[i_] * lda + (k0g) + akseg * 8); \
        cp16(sB_ + b_dst + (uint32_t)i_ * 2048u, Bb + (size_t)((k0g) + kroww + i_ * 8) * DIM); \
    } \
} while (0)

    const int wm = wid & 1, wn = wid >> 1;
    const int m_off = wm * 64;
    uint32_t aoffc[4], axorl[4];
#pragma unroll
    for (int mi = 0; mi < 4; mi++) {
        int ar = m_off + mi * 16 + (lane & 15);
        aoffc[mi] = (uint32_t)(ar * 128);
        axorl[mi] = (uint32_t)((ar & 7) << 4);
    }
    const uint32_t akp = (uint32_t)((lane >> 4) * 16);
    const int kr0 = ((lane >> 3) & 1) * 8 + (lane & 7);
    const int noct = (lane >> 4) & 1;
    uint32_t boffc[4];
#pragma unroll
    for (int g = 0; g < 4; g++) {
        int nb = wn * 64 + g * 16;
        uint32_t nbyte = (uint32_t)((nb + noct * 8) * 2);
        boffc[g] = 16384u + (uint32_t)(kr0 * 256) + (nbyte ^ (uint32_t)((kr0 & 7) << 4));
    }

    float acc[32][4];
#pragma unroll
    for (int i = 0; i < 32; i++)
#pragma unroll
        for (int j = 0; j < 4; j++) acc[i][j] = 0.0f;

    const int NCH = kt / 64;
    DISSUE(0, 0);  COMMIT();
    DISSUE(64, 1); COMMIT();
    for (int it = 0; it < NCH; it++) {
        WAIT1();
        __syncthreads();
        if (it + 2 < NCH) DISSUE((it + 2) * 64, (it + 2) % 3);
        COMMIT();
        const uint32_t sb = sbase + (uint32_t)(it % 3) * 32768u;
#pragma unroll
        for (int ks = 0; ks < 4; ks++) {
            uint32_t af[4][4];
#pragma unroll
            for (int mi = 0; mi < 4; mi++)
                ldm4(af[mi], sb + aoffc[mi] + (((uint32_t)(ks * 32) + akp) ^ axorl[mi]));
            uint32_t bf[4][4];
#pragma unroll
            for (int g = 0; g < 4; g++)
                ldm4t(bf[g], sb + boffc[g] + (uint32_t)(ks * 4096));
#pragma unroll
            for (int mi = 0; mi < 4; mi++)
#pragma unroll
                for (int nt = 0; nt < 8; nt++)
                    mma16(acc[mi * 8 + nt], af[mi],
                          bf[nt >> 1][(nt & 1) * 2], bf[nt >> 1][(nt & 1) * 2 + 1]);
        }
    }
#undef DISSUE

    const int rbase = lane >> 2;
    const int cbase = (lane & 3) * 2;
#pragma unroll
    for (int mi = 0; mi < 4; mi++) {
#pragma unroll
        for (int h = 0; h < 2; h++) {
            const int m = m0 + m_off + mi * 16 + rbase + h * 8;
            if (m >= rows) continue;
            int tok; float w;
            if (list) { tok = list[m]; w = wtp[m]; }
            else      { tok = m; w = 1.0f; }
            float* orow = outp + (size_t)tok * DIM;
#pragma unroll
            for (int nt = 0; nt < 8; nt++) {
                const int d = n0f + wn * 64 + nt * 8 + cbase;
                float bb0 = b2[d]     + (b2b ? b2b[d]     : 0.0f);
                float bb1 = b2[d + 1] + (b2b ? b2b[d + 1] : 0.0f);
                atomicAdd(orow + d,     w * (acc[mi * 8 + nt][h * 2 + 0] + bb0));
                atomicAdd(orow + d + 1, w * (acc[mi * 8 + nt][h * 2 + 1] + bb1));
            }
        }
    }
}

// ================= persistent drivers =================
#define GRID_P 304

__global__ void __launch_bounds__(128, 2) up_persist(
    const float* __restrict__ rgb, const float* __restrict__ rb1,
    const float* __restrict__ sgb, const float* __restrict__ sb1)
{
    extern __shared__ char dynsm[];
    __shared__ int s_row[128];
    const int tid = threadIdx.x, wid = tid >> 5, lane = tid & 31;
    const uint32_t sbase = smem_u32(dynsm);

    for (int idx = blockIdx.x; idx < 8192 + 1024; idx += gridDim.x) {
        if (idx < 8192) {
            int e = idx >> 9, rem = idx & 511, mt = rem >> 4, nt = rem & 15;
            int rows = g_cnt[e];
            if (mt * 128 >= rows) continue;
            tile_up(mt * 128, nt * 64, rows, g_list + e * CAP,
                    g_half + ORG  + (size_t)e * DIM * FF,
                    g_half + ORW1 + (size_t)e * DIM * FF,
                    rgb + (size_t)e * FF, rb1 + (size_t)e * FF,
                    g_hh + (size_t)e * CAP * FF, FF,
                    sbase, s_row, tid, wid, lane);
        } else {
            int i2 = idx - 8192;
            int e = i2 >> 9, rem = i2 & 511, mt = rem >> 4, nt = rem & 15;
            tile_up(mt * 128, nt * 64, N_TOK, nullptr,
                    g_half + OSG  + (size_t)e * DIM * FF,
                    g_half + OSW1 + (size_t)e * DIM * FF,
                    sgb + (size_t)e * FF, sb1 + (size_t)e * FF,
                    g_hs + (size_t)e * FF, 2 * FF,
                    sbase, s_row, tid, wid, lane);
        }
    }
}

__global__ void __launch_bounds__(128, 2) down_persist(
    const float* __restrict__ rb2, const float* __restrict__ sb2,
    float* __restrict__ outp)
{
    extern __shared__ char dynsm[];
    __shared__ int s_row[128];
    const int tid = threadIdx.x, wid = tid >> 5, lane = tid & 31;
    const uint32_t sbase = smem_u32(dynsm);

    for (int idx = blockIdx.x; idx < 8192 + 512; idx += gridDim.x) {
        if (idx < 8192) {
            int e = idx >> 9, mt = (idx >> 4) & 31, nt = idx & 15;
            int rows = g_cnt[e];
            if (mt * 128 >= rows) continue;
            tile_down(mt * 128, nt * 128, rows, FF,
                      g_hh + (size_t)e * CAP * FF, FF,
                      g_list + e * CAP, g_wt + e * CAP,
                      g_half + ORW2 + (size_t)e * FF * DIM,
                      rb2 + (size_t)e * DIM, nullptr, outp,
                      sbase, s_row, tid, wid, lane);
        } else {
            int i2 = idx - 8192;
            int mt = i2 >> 4, nt = i2 & 15;
            tile_down(mt * 128, nt * 128, N_TOK, 2 * FF,
                      g_hs, 2 * FF,
                      nullptr, nullptr,
                      g_half + OSW2,
                      sb2, sb2 + DIM, outp,
                      sbase, s_row, tid, wid, lane);
        }
    }
}

// ---------- launch ----------
extern "C" void kernel_launch(void* const* d_in, const int* in_sizes, int n_in,
                              void* d_out, int out_size) {
    const float* x   = (const float*)d_in[0];
    const float* wa  = (const float*)d_in[1];
    const float* rg  = (const float*)d_in[2];
    const float* rgb = (const float*)d_in[3];
    const float* rw1 = (const float*)d_in[4];
    const float* rb1 = (const float*)d_in[5];
    const float* rw2 = (const float*)d_in[6];
    const float* rb2 = (const float*)d_in[7];
    const float* sg  = (const float*)d_in[8];
    const float* sgb = (const float*)d_in[9];
    const float* sw1 = (const float*)d_in[10];
    const float* sb1 = (const float*)d_in[11];
    const float* sw2 = (const float*)d_in[12];
    const float* sb2 = (const float*)d_in[13];
    float* out = (float*)d_out;

    const int smem = 3 * 32768;
    cudaFuncSetAttribute(up_persist,   cudaFuncAttributeMaxDynamicSharedMemorySize, smem);
    cudaFuncSetAttribute(down_persist, cudaFuncAttributeMaxDynamicSharedMemorySize, smem);

    zero_cnt_kernel<<<1, 32>>>();
    router_kernel<<<N_TOK / 4, 128>>>(x, wa);

    auto cvt = [&](const float* s, size_t off, size_t n) {
        cvt_kernel<<<(unsigned)(n / 1024), 256>>>(s, off, n);
    };
    cvt(x,   OXH,  (size_t)N_TOK * DIM);
    cvt(rg,  ORG,  (size_t)NE * DIM * FF);
    cvt(rw1, ORW1, (size_t)NE * DIM * FF);
    cvt(rw2, ORW2, (size_t)NE * FF * DIM);
    cvt(sg,  OSG,  (size_t)2 * DIM * FF);
    cvt(sw1, OSW1, (size_t)2 * DIM * FF);
    cvt(sw2, OSW2, (size_t)2 * FF * DIM);

    copy_x_kernel<<<(N_TOK * DIM) / 1024, 256>>>(x, out);

    up_persist<<<GRID_P, 128, smem>>>(rgb, rb1, sgb, sb1);
    down_persist<<<GRID_P, 128, smem>>>(rb2, sb2, out);
}